// round 7
// baseline (speedup 1.0000x reference)
#include <cuda_runtime.h>
#include <cuda_bf16.h>
#include <cstdint>

// out[b,d,n] = w[d] * in[b,d,n];  B=8, D=2048, N=2048, fp32.
// R6: LDG.128 loads (proven) + bulk-async 32KB store (cp.async.bulk S->G)
// to test DRAM write-burst granularity. No mbarrier — hang-proof.

static constexpr int B = 8;
static constexpr int D = 2048;
static constexpr int N = 2048;
static constexpr int THREADS = 256;
static constexpr int F4_PER_THREAD = 8;
static constexpr int TILE_F4 = THREADS * F4_PER_THREAD;        // 2048 float4
static constexpr int TILE_FLOATS = TILE_F4 * 4;                // 8192 = 4 rows
static constexpr int TILE_BYTES = TILE_FLOATS * 4;             // 32768
static constexpr int F4_PER_ROW = N / 4;                       // 512
static constexpr long long NUM_TILES =
    (long long)B * D * N / TILE_FLOATS;                        // 4096

__device__ __forceinline__ uint32_t smem_u32(const void* p) {
    uint32_t a;
    asm("{ .reg .u64 t; cvta.to.shared.u64 t, %1; cvt.u32.u64 %0, t; }"
        : "=r"(a) : "l"(p));
    return a;
}

__global__ void __launch_bounds__(THREADS)
channel_scale_kernel(const float4* __restrict__ in,
                     const float*  __restrict__ w,
                     float*        __restrict__ out)
{
    __shared__ alignas(128) float4 tile4[TILE_F4];

    int tid = threadIdx.x;
    long long tile_id = blockIdx.x;
    long long base_f4 = tile_id * TILE_F4;          // global float4 offset
    int base_row = (int)((base_f4 >> 9));           // global row index b*D+d

    // Front-batched LDG.128 x8 per thread (proven 75%-of-peak load path).
    float4 v[F4_PER_THREAD];
#pragma unroll
    for (int k = 0; k < F4_PER_THREAD; k++) {
        v[k] = in[base_f4 + tid + k * THREADS];
    }

#pragma unroll
    for (int k = 0; k < F4_PER_THREAD; k++) {
        int if4 = tid + k * THREADS;                // 0..2047 within tile
        int d = (base_row + (if4 / F4_PER_ROW)) & (D - 1);
        float s = __ldg(w + d);                     // 8 KB, L2-resident
        v[k].x *= s; v[k].y *= s; v[k].z *= s; v[k].w *= s;
        tile4[if4] = v[k];
    }
    __syncthreads();

    // Single 32KB bulk store S->G from one thread.
    if (tid == 0) {
        uint32_t tile_sa = smem_u32(tile4);
        asm volatile("fence.proxy.async.shared::cta;" ::: "memory");
        asm volatile("cp.async.bulk.global.shared::cta.bulk_group [%0], [%1], %2;"
                     :: "l"(out + tile_id * TILE_FLOATS), "r"(tile_sa),
                        "r"((uint32_t)TILE_BYTES) : "memory");
        asm volatile("cp.async.bulk.commit_group;" ::: "memory");
        asm volatile("cp.async.bulk.wait_group 0;" ::: "memory");
    }
    __syncthreads();
}

extern "C" void kernel_launch(void* const* d_in, const int* in_sizes, int n_in,
                              void* d_out, int out_size)
{
    const float4* in = (const float4*)d_in[0];   // inputs [B, D, N] fp32
    const float*  w  = (const float*)d_in[1];    // attention_weights [D] fp32
    float* out = (float*)d_out;

    channel_scale_kernel<<<(unsigned)NUM_TILES, THREADS>>>(in, w, out);
}